// round 4
// baseline (speedup 1.0000x reference)
#include <cuda_runtime.h>
#include <cuda_fp16.h>
#include <cstdint>

#define B_ 256
#define I_ 1152
#define N_ 10
#define D_ 16
#define K_ 8

// u_hat scratch, layout [b][n][i][d], fp16 = 94 MB
__device__ __half g_uhat[(size_t)B_ * N_ * I_ * D_];

// ---------------- helpers ----------------
__device__ __forceinline__ unsigned long long pack2(float a, float b) {
    unsigned long long r;
    asm("mov.b64 %0, {%1, %2};" : "=l"(r) : "f"(a), "f"(b));
    return r;
}
__device__ __forceinline__ unsigned long long fma2(unsigned long long a,
                                                   unsigned long long b,
                                                   unsigned long long c) {
    unsigned long long r;
    asm("fma.rn.f32x2 %0, %1, %2, %3;" : "=l"(r) : "l"(a), "l"(b), "l"(c));
    return r;
}
__device__ __forceinline__ unsigned int cvt2h(unsigned long long v) {
    float lo, hi;
    asm("mov.b64 {%0, %1}, %2;" : "=f"(lo), "=f"(hi) : "l"(v));
    __half2 h = __floats2half2_rn(lo, hi);
    return *reinterpret_cast<unsigned int*>(&h);
}

// ---------------- kernel 1: u_hat = einsum('nidk,bik->bnid') fp16 -------------
// Grid 576: (i-group of 8) x (b-quarter of 64). 512 threads, 2 CTAs/SM.
__global__ __launch_bounds__(512, 2) void k_uhat(const float* __restrict__ x,
                                                 const float* __restrict__ W) {
    __shared__ unsigned long long sW[8 * 642];  // 41,088 B
    const int tid = threadIdx.x;
    const int ig = blockIdx.x >> 2;
    const int bq = blockIdx.x & 3;
    const int i0 = ig * 8;

    for (int idx = tid; idx < 5120; idx += 512) {
        int k    = idx & 7;
        int dp   = (idx >> 3) & 7;
        int n    = (idx >> 6) % 10;
        int iloc = idx / 640;
        const float* wp = W + ((((size_t)n * I_ + i0 + iloc) * D_ + dp * 2) * K_ + k);
        sW[iloc * 642 + n * 64 + dp * 8 + k] = pack2(wp[0], wp[K_]);
    }
    __syncthreads();

    const int iloc = tid & 7;
    const int b    = bq * 64 + (tid >> 3);

    float xr[8];
    {
        const float4* xp = (const float4*)(x + ((size_t)b * I_ + i0 + iloc) * K_);
        float4 a = xp[0], c = xp[1];
        xr[0] = a.x; xr[1] = a.y; xr[2] = a.z; xr[3] = a.w;
        xr[4] = c.x; xr[5] = c.y; xr[6] = c.z; xr[7] = c.w;
    }

    const unsigned long long* wrow = sW + iloc * 642;
#pragma unroll 1
    for (int n = 0; n < 10; n++) {
        unsigned long long acc[8];
#pragma unroll
        for (int dp = 0; dp < 8; dp++) acc[dp] = 0ull;
#pragma unroll
        for (int k = 0; k < 8; k++) {
            unsigned long long xx = pack2(xr[k], xr[k]);
#pragma unroll
            for (int dp = 0; dp < 8; dp++)
                acc[dp] = fma2(wrow[n * 64 + dp * 8 + k], xx, acc[dp]);
        }
        unsigned int r[8];
#pragma unroll
        for (int dp = 0; dp < 8; dp++) r[dp] = cvt2h(acc[dp]);
        uint4* op = (uint4*)(g_uhat +
            (((size_t)b * N_ + n) * I_ + i0 + iloc) * D_);
        op[0] = make_uint4(r[0], r[1], r[2], r[3]);
        op[1] = make_uint4(r[4], r[5], r[6], r[7]);
    }
}

// ---------------- kernel 2: fused routing, 4-CTA cluster per b ----------------
#define RT_THREADS 384
#define QI_ 288                      // i per CTA
#define NSTRIDE 2312                 // u32 stride per n (288*8 + 8 pad)
#define U_WORDS (N_ * NSTRIDE)       // 23120
#define SPART_STRIDE 168
#define SMEM_WORDS (U_WORDS + 12 * SPART_STRIDE + 2 * 160 + 160 + 160)
#define SMEM_BYTES (SMEM_WORDS * 4)  // 103,104 B -> 2 CTAs/SM

__global__ __launch_bounds__(RT_THREADS, 2) __cluster_dims__(4, 1, 1)
void k_route_all(float* __restrict__ out) {
    extern __shared__ unsigned int smem[];
    float* smf = (float*)smem;
    const int tid = threadIdx.x;
    const int b = blockIdx.x >> 2;
    unsigned int rank;
    asm("mov.u32 %0, %%cluster_ctarank;" : "=r"(rank));

    // ---- load u slice: for each n, i in [rank*288, rank*288+288), contiguous
    for (int t = tid; t < 5760; t += RT_THREADS) {
        int n   = t / 576;
        int rem = t - n * 576;           // uint4 within this n's slice
        const uint4* gp = (const uint4*)g_uhat +
            (((size_t)b * N_ + n) * I_ + rank * QI_) * 2 + rem;
        int iloc = rem >> 1, dh = rem & 1;
        *(uint4*)&smem[n * NSTRIDE + iloc * 8 + dh * 4] = *gp;
    }

    const int w = tid >> 5, lane = tid & 31;
    const int il = lane >> 2, dq = lane & 3;

    float* sPart = smf + U_WORDS;             // [12][168]
    float* ssum  = sPart + 12 * SPART_STRIDE; // [2][160] ping-pong
    float* stot  = ssum + 2 * 160;            // [160]
    float* ocum  = stot + 160;                // [160]

    unsigned int ssum_sa = (unsigned int)__cvta_generic_to_shared(ssum);
    unsigned int peer[3];
#pragma unroll
    for (int p = 0; p < 3; p++)
        asm("mapa.shared::cluster.u32 %0, %1, %2;"
            : "=r"(peer[p]) : "r"(ssum_sa), "r"(rank ^ (unsigned)(p + 1)));

    __syncthreads();

#pragma unroll 1
    for (int r = 0; r < 3; r++) {
        const int buf = r & 1;
        float sp[N_][4];
#pragma unroll
        for (int n = 0; n < N_; n++)
#pragma unroll
            for (int q = 0; q < 4; q++) sp[n][q] = 0.0f;

#pragma unroll 1
        for (int round = 0; round < 3; round++) {
            const int abase = (round * 96 + w * 8 + il) * 8 + dq * 2;
            float c[N_];
            if (r == 0) {
#pragma unroll
                for (int n = 0; n < N_; n++) c[n] = 0.1f;
            } else {
#pragma unroll
                for (int n = 0; n < N_; n++) {
                    uint2 v = *(const uint2*)&smem[n * NSTRIDE + abase];
                    float2 f0 = __half22float2(*(const __half2*)&v.x);
                    float2 f1 = __half22float2(*(const __half2*)&v.y);
                    float4 o = *(const float4*)&ocum[n * 16 + dq * 4];
                    c[n] = f0.x * o.x + f0.y * o.y + f1.x * o.z + f1.y * o.w;
                }
#pragma unroll
                for (int n = 0; n < N_; n++) {
                    c[n] += __shfl_xor_sync(0xffffffffu, c[n], 1);
                    c[n] += __shfl_xor_sync(0xffffffffu, c[n], 2);
                }
                float m = c[0];
#pragma unroll
                for (int n = 1; n < N_; n++) m = fmaxf(m, c[n]);
                float sum = 0.0f;
#pragma unroll
                for (int n = 0; n < N_; n++) { c[n] = __expf(c[n] - m); sum += c[n]; }
                float inv = __fdividef(1.0f, sum);
#pragma unroll
                for (int n = 0; n < N_; n++) c[n] *= inv;
            }
            // accumulate (reload u from smem; keeps regs low)
#pragma unroll
            for (int n = 0; n < N_; n++) {
                uint2 v = *(const uint2*)&smem[n * NSTRIDE + abase];
                float2 f0 = __half22float2(*(const __half2*)&v.x);
                float2 f1 = __half22float2(*(const __half2*)&v.y);
                sp[n][0] += c[n] * f0.x;
                sp[n][1] += c[n] * f0.y;
                sp[n][2] += c[n] * f1.x;
                sp[n][3] += c[n] * f1.y;
            }
        }

#pragma unroll
        for (int ofs = 4; ofs <= 16; ofs <<= 1)
#pragma unroll
            for (int n = 0; n < N_; n++)
#pragma unroll
                for (int q = 0; q < 4; q++)
                    sp[n][q] += __shfl_xor_sync(0xffffffffu, sp[n][q], ofs);

        if (il == 0) {
#pragma unroll
            for (int n = 0; n < N_; n++)
                *(float4*)&sPart[w * SPART_STRIDE + n * 16 + dq * 4] =
                    make_float4(sp[n][0], sp[n][1], sp[n][2], sp[n][3]);
        }
        __syncthreads();

        if (tid < 160) {
            float s = 0.0f;
#pragma unroll
            for (int ww = 0; ww < 12; ww++) s += sPart[ww * SPART_STRIDE + tid];
            ssum[buf * 160 + tid] = s;
        }
        asm volatile("barrier.cluster.arrive.aligned;" ::: "memory");
        asm volatile("barrier.cluster.wait.aligned;" ::: "memory");

        if (tid < 160) {
            float tot = ssum[buf * 160 + tid];
#pragma unroll
            for (int p = 0; p < 3; p++) {
                float pv;
                unsigned int pa = peer[p] + (unsigned int)(buf * 160 + tid) * 4u;
                asm volatile("ld.shared::cluster.f32 %0, [%1];" : "=f"(pv) : "r"(pa));
                tot += pv;
            }
            stot[tid] = tot;
        }
        __syncthreads();

        if (tid < 160) {
            const int n = tid >> 4;
            float ns = 0.0f;
#pragma unroll
            for (int j = 0; j < 16; j++) {
                float t = stot[n * 16 + j];
                ns += t * t;
            }
            float f = sqrtf(ns) / (1.0f + ns);
            float val = stot[tid] * f;
            if (r < 2) ocum[tid] = (r == 0) ? val : ocum[tid] + val;
            else if (rank == 0) out[b * 160 + tid] = val;
        }
        __syncthreads();
    }
    asm volatile("barrier.cluster.arrive.aligned;" ::: "memory");
    asm volatile("barrier.cluster.wait.aligned;" ::: "memory");
}

// ---------------- launch ----------------
extern "C" void kernel_launch(void* const* d_in, const int* in_sizes, int n_in,
                              void* d_out, int out_size) {
    const float* x = (const float*)d_in[0];   // inputs [B, I, Din]
    const float* W = (const float*)d_in[1];   // W      [N, I, D, Din]
    if (n_in >= 2 && in_sizes[0] == N_ * I_ * D_ * K_) {
        const float* t = x; x = W; W = t;
    }
    float* out = (float*)d_out;

    cudaFuncSetAttribute(k_route_all,
                         cudaFuncAttributeMaxDynamicSharedMemorySize, SMEM_BYTES);

    k_uhat<<<576, 512>>>(x, W);
    k_route_all<<<4 * B_, RT_THREADS, SMEM_BYTES>>>(out);
}

// round 5
// speedup vs baseline: 1.0531x; 1.0531x over previous
#include <cuda_runtime.h>
#include <cuda_fp16.h>
#include <cstdint>

#define B_ 256
#define I_ 1152
#define N_ 10
#define D_ 16
#define K_ 8

// u_hat scratch, layout [b][n][i][d], fp16 = 94 MB
__device__ __half g_uhat[(size_t)B_ * N_ * I_ * D_];

// ---------------- helpers ----------------
__device__ __forceinline__ unsigned long long pack2(float a, float b) {
    unsigned long long r;
    asm("mov.b64 %0, {%1, %2};" : "=l"(r) : "f"(a), "f"(b));
    return r;
}
__device__ __forceinline__ unsigned long long fma2(unsigned long long a,
                                                   unsigned long long b,
                                                   unsigned long long c) {
    unsigned long long r;
    asm("fma.rn.f32x2 %0, %1, %2, %3;" : "=l"(r) : "l"(a), "l"(b), "l"(c));
    return r;
}
__device__ __forceinline__ unsigned int cvt2h(unsigned long long v) {
    float lo, hi;
    asm("mov.b64 {%0, %1}, %2;" : "=f"(lo), "=f"(hi) : "l"(v));
    __half2 h = __floats2half2_rn(lo, hi);
    return *reinterpret_cast<unsigned int*>(&h);
}

// ---------------- kernel 1: u_hat = einsum('nidk,bik->bnid') fp16 -------------
// Grid 576 = 144 i-groups x 4 b-quarters. 320 threads = (iloc 8) x (n 10) x (dq 4).
// x staged in smem duplicated as (x,x) u64 -> hot-loop LDS.64 is warp-broadcast.
// W held in registers (16 u64 of d-paired values).
__global__ __launch_bounds__(320, 2) void k_uhat(const float* __restrict__ x,
                                                 const float* __restrict__ W) {
    __shared__ unsigned long long sx[64 * 64];  // [bl][il*8+k], 32 KB
    const int tid = threadIdx.x;
    const int ig = blockIdx.x >> 2;
    const int bq = blockIdx.x & 3;
    const int i0 = ig * 8;
    const int b0 = bq * 64;

    // stage x (fully coalesced reads), duplicate each float into u64 lanes
    for (int t = tid; t < 4096; t += 320) {
        int bl = t >> 6, rem = t & 63;
        float v = x[(size_t)(b0 + bl) * (I_ * K_) + i0 * K_ + rem];
        sx[t] = pack2(v, v);
    }

    const int dq   = tid & 3;
    const int n    = (tid >> 2) % 10;
    const int iloc = tid / 40;

    // W regs: w2[k][p] = (W[d0+2p, k], W[d0+2p+1, k]), d0 = dq*4
    unsigned long long w2[8][2];
    {
        const float4* wp = (const float4*)(W +
            (((size_t)n * I_ + i0 + iloc) * D_ + dq * 4) * K_);
        float4 r0a = wp[0], r0b = wp[1];
        float4 r1a = wp[2], r1b = wp[3];
        float4 r2a = wp[4], r2b = wp[5];
        float4 r3a = wp[6], r3b = wp[7];
        w2[0][0] = pack2(r0a.x, r1a.x); w2[1][0] = pack2(r0a.y, r1a.y);
        w2[2][0] = pack2(r0a.z, r1a.z); w2[3][0] = pack2(r0a.w, r1a.w);
        w2[4][0] = pack2(r0b.x, r1b.x); w2[5][0] = pack2(r0b.y, r1b.y);
        w2[6][0] = pack2(r0b.z, r1b.z); w2[7][0] = pack2(r0b.w, r1b.w);
        w2[0][1] = pack2(r2a.x, r3a.x); w2[1][1] = pack2(r2a.y, r3a.y);
        w2[2][1] = pack2(r2a.z, r3a.z); w2[3][1] = pack2(r2a.w, r3a.w);
        w2[4][1] = pack2(r2b.x, r3b.x); w2[5][1] = pack2(r2b.y, r3b.y);
        w2[6][1] = pack2(r2b.z, r3b.z); w2[7][1] = pack2(r2b.w, r3b.w);
    }
    __syncthreads();

    __half* gout = g_uhat +
        (((size_t)b0 * N_ + n) * I_ + i0 + iloc) * D_ + dq * 4;
    const size_t bstride = (size_t)N_ * I_ * D_;

#pragma unroll 2
    for (int bl = 0; bl < 64; bl++) {
        const unsigned long long* xr = sx + bl * 64 + iloc * 8;
        unsigned long long a0 = 0ull, a1 = 0ull;
#pragma unroll
        for (int k = 0; k < 8; k++) {
            unsigned long long xx = xr[k];
            a0 = fma2(w2[k][0], xx, a0);
            a1 = fma2(w2[k][1], xx, a1);
        }
        uint2 r;
        r.x = cvt2h(a0);
        r.y = cvt2h(a1);
        *(uint2*)(gout + (size_t)bl * bstride) = r;
    }
}

// ---------------- kernel 2: fused routing, 4-CTA cluster per b ----------------
#define RT_THREADS 288
#define QI_ 288
#define NSTRIDE 2312                  // u32 words per n-block (288*8 + pad)
#define U_WORDS (N_ * NSTRIDE)        // 23120
#define CB_WORDS 2920                 // c[n][i] stride 292 (union: sPart 9*168)
#define SMEM_WORDS (U_WORDS + CB_WORDS + 2 * 160 + 160 + 160)
#define SMEM_BYTES (SMEM_WORDS * 4)   // 106,720 B -> 2 CTAs/SM

__global__ __launch_bounds__(RT_THREADS, 2) __cluster_dims__(4, 1, 1)
void k_route_all(float* __restrict__ out) {
    extern __shared__ unsigned int smem[];
    float* smf = (float*)smem;
    const int tid = threadIdx.x;
    const int b = blockIdx.x >> 2;
    unsigned int rank;
    asm("mov.u32 %0, %%cluster_ctarank;" : "=r"(rank));

    // load u slice [n][i_local][d], contiguous per n
    for (int t = tid; t < 5760; t += RT_THREADS) {
        int n   = t / 576;
        int rem = t - n * 576;
        const uint4* gp = (const uint4*)g_uhat +
            (((size_t)b * N_ + n) * I_ + rank * QI_) * 2 + rem;
        uint4 v = *gp;
        int il = rem >> 1, dh = rem & 1;
        *(uint4*)&smem[n * NSTRIDE + il * 8 + dh * 4] = v;
    }

    float* cbuf  = smf + U_WORDS;        // c[n][i], stride 292
    float* sPart = cbuf;                 // union (guarded by syncthreads)
    float* ssum  = smf + U_WORDS + CB_WORDS;  // [2][160]
    float* stot  = ssum + 320;
    float* ocum  = stot + 160;

    unsigned int ssum_sa = (unsigned int)__cvta_generic_to_shared(ssum);
    unsigned int peer[3];
#pragma unroll
    for (int p = 0; p < 3; p++)
        asm("mapa.shared::cluster.u32 %0, %1, %2;"
            : "=r"(peer[p]) : "r"(ssum_sa), "r"(rank ^ (unsigned)(p + 1)));

    const int w = tid >> 5, lane = tid & 31;
    const int il = lane >> 2, dq = lane & 3;

    __syncthreads();

#pragma unroll 1
    for (int r = 0; r < 3; r++) {
        // ---- sweep A: per-thread softmax coefficients (r >= 1) ----
        if (r > 0) {
            float lg[N_];
#pragma unroll
            for (int n = 0; n < N_; n++) {
                const unsigned int* up = &smem[n * NSTRIDE + tid * 8];
                uint4 v0 = *(const uint4*)up;
                uint4 v1 = *(const uint4*)(up + 4);
                const float4* op = (const float4*)&ocum[n * 16];
                float4 o0 = op[0], o1 = op[1], o2 = op[2], o3 = op[3];
                float2 a0 = __half22float2(*(const __half2*)&v0.x);
                float2 a1 = __half22float2(*(const __half2*)&v0.y);
                float2 a2 = __half22float2(*(const __half2*)&v0.z);
                float2 a3 = __half22float2(*(const __half2*)&v0.w);
                float2 a4 = __half22float2(*(const __half2*)&v1.x);
                float2 a5 = __half22float2(*(const __half2*)&v1.y);
                float2 a6 = __half22float2(*(const __half2*)&v1.z);
                float2 a7 = __half22float2(*(const __half2*)&v1.w);
                float p0 = a0.x * o0.x + a0.y * o0.y + a1.x * o0.z + a1.y * o0.w;
                float p1 = a2.x * o1.x + a2.y * o1.y + a3.x * o1.z + a3.y * o1.w;
                float p2 = a4.x * o2.x + a4.y * o2.y + a5.x * o2.z + a5.y * o2.w;
                float p3 = a6.x * o3.x + a6.y * o3.y + a7.x * o3.z + a7.y * o3.w;
                lg[n] = (p0 + p1) + (p2 + p3);
            }
            float m = lg[0];
#pragma unroll
            for (int n = 1; n < N_; n++) m = fmaxf(m, lg[n]);
            float sum = 0.0f;
#pragma unroll
            for (int n = 0; n < N_; n++) { lg[n] = __expf(lg[n] - m); sum += lg[n]; }
            float inv = __fdividef(1.0f, sum);
#pragma unroll
            for (int n = 0; n < N_; n++)
                cbuf[n * 292 + tid] = lg[n] * inv;
            __syncthreads();
        }

        // ---- sweep B: weighted accumulation ----
        float sp[N_][4];
#pragma unroll
        for (int n = 0; n < N_; n++)
#pragma unroll
            for (int q = 0; q < 4; q++) sp[n][q] = 0.0f;

#pragma unroll 1
        for (int round = 0; round < 4; round++) {
            const int iL = round * 72 + w * 8 + il;
            const int abase = iL * 8 + dq * 2;
#pragma unroll
            for (int n = 0; n < N_; n++) {
                uint2 v = *(const uint2*)&smem[n * NSTRIDE + abase];
                float2 f0 = __half22float2(*(const __half2*)&v.x);
                float2 f1 = __half22float2(*(const __half2*)&v.y);
                float cv = (r == 0) ? 0.1f : cbuf[n * 292 + iL];
                sp[n][0] += cv * f0.x;
                sp[n][1] += cv * f0.y;
                sp[n][2] += cv * f1.x;
                sp[n][3] += cv * f1.y;
            }
        }
        __syncthreads();   // all cbuf reads done before sPart overwrite (union)

        // reduce sp over il lanes
#pragma unroll
        for (int ofs = 4; ofs <= 16; ofs <<= 1)
#pragma unroll
            for (int n = 0; n < N_; n++)
#pragma unroll
                for (int q = 0; q < 4; q++)
                    sp[n][q] += __shfl_xor_sync(0xffffffffu, sp[n][q], ofs);

        if (il == 0) {
#pragma unroll
            for (int n = 0; n < N_; n++)
                *(float4*)&sPart[w * 168 + n * 16 + dq * 4] =
                    make_float4(sp[n][0], sp[n][1], sp[n][2], sp[n][3]);
        }
        __syncthreads();

        const int buf = r & 1;
        if (tid < 160) {
            float s = 0.0f;
#pragma unroll
            for (int ww = 0; ww < 9; ww++) s += sPart[ww * 168 + tid];
            ssum[buf * 160 + tid] = s;
        }
        asm volatile("barrier.cluster.arrive.aligned;" ::: "memory");
        asm volatile("barrier.cluster.wait.aligned;" ::: "memory");

        if (tid < 160) {
            float tot = ssum[buf * 160 + tid];
#pragma unroll
            for (int p = 0; p < 3; p++) {
                float pv;
                unsigned int pa = peer[p] + (unsigned int)(buf * 160 + tid) * 4u;
                asm volatile("ld.shared::cluster.f32 %0, [%1];" : "=f"(pv) : "r"(pa));
                tot += pv;
            }
            stot[tid] = tot;
        }
        __syncthreads();

        if (tid < 160) {
            const int n = tid >> 4;
            float ns = 0.0f;
#pragma unroll
            for (int j = 0; j < 16; j++) {
                float t = stot[n * 16 + j];
                ns += t * t;
            }
            float f = sqrtf(ns) / (1.0f + ns);
            float val = stot[tid] * f;
            if (r < 2) ocum[tid] = (r == 0) ? val : ocum[tid] + val;
            else if (rank == 0) out[b * 160 + tid] = val;
        }
        __syncthreads();
    }
    asm volatile("barrier.cluster.arrive.aligned;" ::: "memory");
    asm volatile("barrier.cluster.wait.aligned;" ::: "memory");
}

// ---------------- launch ----------------
extern "C" void kernel_launch(void* const* d_in, const int* in_sizes, int n_in,
                              void* d_out, int out_size) {
    const float* x = (const float*)d_in[0];   // inputs [B, I, Din]
    const float* W = (const float*)d_in[1];   // W      [N, I, D, Din]
    if (n_in >= 2 && in_sizes[0] == N_ * I_ * D_ * K_) {
        const float* t = x; x = W; W = t;
    }
    float* out = (float*)d_out;

    cudaFuncSetAttribute(k_route_all,
                         cudaFuncAttributeMaxDynamicSharedMemorySize, SMEM_BYTES);

    k_uhat<<<576, 320>>>(x, W);
    k_route_all<<<4 * B_, RT_THREADS, SMEM_BYTES>>>(out);
}